// round 12
// baseline (speedup 1.0000x reference)
#include <cuda_runtime.h>
#include <cuda_fp16.h>
#include <math.h>
#include <stddef.h>
#include <stdint.h>

// ---------------- problem constants ----------------
#define DM     2048
#define DIP    8512
#define NPAD1  8704            // DIP padded to 256 for N-tiles
#define DIN    4096
#define CONVD  4352
#define NH     64
#define HD     64
#define DS     128
#define LTOT   2048
#define NBATCH 2
#define ROWS   (NBATCH*LTOT)   // 4096
#define CK     64
#define NCHUNK (LTOT/CK)

// ---------------- scratch ----------------
__device__ float g_zx [(size_t)ROWS*DIP];
__device__ float g_xbc[(size_t)ROWS*CONVD];
__device__ float g_dt [ROWS*NH];
__device__ float g_y  [(size_t)ROWS*DIN];
// fp16 split A = [Ah|Al] along K (row stride 2K); B single-copy Bh [n][K]
__device__ __half g_hA1[(size_t)ROWS*2*DM];
__device__ __half g_hB1[(size_t)NPAD1*DM];
__device__ __half g_hA2[(size_t)ROWS*2*DIN];
__device__ __half g_hB2[(size_t)DM*DIN];

__device__ __forceinline__ float softplus_f(float x) {
    return (x > 20.f) ? x : log1pf(expf(x));
}
__device__ __forceinline__ float silu_f(float x) {
    return x / (1.f + expf(-x));
}

// ---------------- split-fp16 conversions ----------------
__global__ void convA(const float* __restrict__ X,
                      __half* __restrict__ A2, int K)
{
    size_t idx = (size_t)blockIdx.x * blockDim.x + threadIdx.x;
    int k = (int)(idx % K);
    size_t m = idx / K;
    float x = X[idx];
    __half h = __float2half_rn(x);
    __half l = __float2half_rn(x - __half2float(h));
    __half* base = A2 + m * (size_t)(2 * K);
    base[k] = h; base[K + k] = l;
}

__global__ void convB(const float* __restrict__ W,
                      __half* __restrict__ B2, int K, int N)
{
    __shared__ float t[32][33];
    int n = blockIdx.x * 32 + threadIdx.x;
    int k = blockIdx.y * 32 + threadIdx.y;
    t[threadIdx.y][threadIdx.x] = (n < N) ? W[(size_t)k * N + n] : 0.f;
    __syncthreads();
    int on = blockIdx.x * 32 + threadIdx.y;
    int ok = blockIdx.y * 32 + threadIdx.x;
    B2[(size_t)on * K + ok] = __float2half_rn(t[threadIdx.x][threadIdx.y]);
}

// ---------------- asm helpers ----------------
__device__ __forceinline__ uint32_t smem_u32(const void* p) {
    uint32_t a;
    asm("{ .reg .u64 t; cvta.to.shared.u64 t, %1; cvt.u32.u64 %0, t; }"
        : "=r"(a) : "l"(p));
    return a;
}
__device__ __forceinline__ void ldsm4(uint32_t& r0, uint32_t& r1,
                                      uint32_t& r2, uint32_t& r3, uint32_t a) {
    asm volatile("ldmatrix.sync.aligned.m8n8.x4.shared.b16 {%0,%1,%2,%3}, [%4];"
                 : "=r"(r0), "=r"(r1), "=r"(r2), "=r"(r3) : "r"(a));
}
__device__ __forceinline__ void sts16(uint32_t a, uint4 v) {
    asm volatile("st.shared.v4.b32 [%0], {%1,%2,%3,%4};"
                 :: "r"(a), "r"(v.x), "r"(v.y), "r"(v.z), "r"(v.w) : "memory");
}
__device__ __forceinline__ void mma16816(float* d, const uint32_t* a,
                                         const uint32_t* b) {
    asm volatile(
        "mma.sync.aligned.m16n8k16.row.col.f32.f16.f16.f32 "
        "{%0,%1,%2,%3}, {%4,%5,%6,%7}, {%8,%9}, {%0,%1,%2,%3};\n"
        : "+f"(d[0]), "+f"(d[1]), "+f"(d[2]), "+f"(d[3])
        : "r"(a[0]), "r"(a[1]), "r"(a[2]), "r"(a[3]),
          "r"(b[0]), "r"(b[1]));
}
__device__ __forceinline__ uint32_t swz128(uint32_t off) {
    return off ^ ((off >> 3) & 0x70);
}

// ---------------- fp16 GEMM (shared-B split): C = (Ah+Al) @ Bh^T ----------
#define GG_STAGE 65536
#define GG_SMEM  (1024 + 2 * GG_STAGE)

__global__ __launch_bounds__(512) void gemm_fp16(
    const __half* __restrict__ A, const __half* __restrict__ B,
    float* __restrict__ C, int K, int Nstore)
{
    extern __shared__ char smem[];
    const uint32_t sb = (smem_u32(smem) + 1023u) & ~1023u;
    const int tid = threadIdx.x;
    const int wid = tid >> 5, lane = tid & 31;
    const int bm = blockIdx.y * 128, bn = blockIdx.x * 256;
    const int wm = (wid & 1) * 64, wn = (wid >> 1) * 32;
    const int nch = K >> 6;

    const uint4* aSrcH[2];
    const uint4* aSrcL[2];
    const uint4* bSrc[4];
    uint32_t aDstH[2], aDstL[2], bDst[4];
#pragma unroll
    for (int j = 0; j < 2; j++) {
        int u = tid + 512 * j;
        int row = u >> 3, seg = u & 7;
        const __half* pa = A + (size_t)(bm + row) * (2 * K) + seg * 8;
        aSrcH[j] = (const uint4*)pa;
        aSrcL[j] = (const uint4*)(pa + K);
        uint32_t sw = swz128(row * 128 + seg * 16);
        aDstH[j] = sw;
        aDstL[j] = sw + 16384;
    }
#pragma unroll
    for (int j = 0; j < 4; j++) {
        int u = tid + 512 * j;
        int row = u >> 3, seg = u & 7;
        bSrc[j] = (const uint4*)(B + (size_t)(bn + row) * K + seg * 8);
        bDst[j] = 32768 + swz128(row * 128 + seg * 16);
    }

    const uint32_t cxA = (((lane & 7) ^ (lane >> 4)) << 4);
    uint32_t aOff[4];
#pragma unroll
    for (int im = 0; im < 4; im++)
        aOff[im] = (wm + im * 16 + (lane & 15)) * 128;
    const uint32_t cxB = (((lane & 7) ^ ((lane >> 3) & 1)) << 4);
    uint32_t bOff[2];
#pragma unroll
    for (int j2 = 0; j2 < 2; j2++)
        bOff[j2] = 32768 + (wn + j2 * 16 + (lane >> 4) * 8 + (lane & 7)) * 128;

    float c[4][4][4];
#pragma unroll
    for (int i = 0; i < 4; i++)
#pragma unroll
        for (int j = 0; j < 4; j++)
#pragma unroll
            for (int r = 0; r < 4; r++) c[i][j][r] = 0.f;

    uint4 rah[2], ral[2], rb[4];
#pragma unroll
    for (int j = 0; j < 2; j++) { rah[j] = aSrcH[j][0]; ral[j] = aSrcL[j][0]; }
#pragma unroll
    for (int j = 0; j < 4; j++) rb[j] = bSrc[j][0];
#pragma unroll
    for (int j = 0; j < 2; j++) { sts16(sb + aDstH[j], rah[j]); sts16(sb + aDstL[j], ral[j]); }
#pragma unroll
    for (int j = 0; j < 4; j++) sts16(sb + bDst[j], rb[j]);
    __syncthreads();

    for (int i = 0; i < nch; i++) {
        const uint32_t cur = sb + (uint32_t)(i & 1) * GG_STAGE;
        const uint32_t nxt = sb + (uint32_t)((i + 1) & 1) * GG_STAGE;

        if (i + 1 < nch) {
            size_t ko = (size_t)(i + 1) * 8;
#pragma unroll
            for (int j = 0; j < 2; j++) { rah[j] = aSrcH[j][ko]; ral[j] = aSrcL[j][ko]; }
#pragma unroll
            for (int j = 0; j < 4; j++) rb[j] = bSrc[j][ko];
        }

#pragma unroll
        for (int ks2 = 0; ks2 < 128; ks2 += 32) {
            uint32_t a[4][4], b[4][2];
#pragma unroll
            for (int j2 = 0; j2 < 2; j2++)
                ldsm4(b[2 * j2][0], b[2 * j2][1], b[2 * j2 + 1][0], b[2 * j2 + 1][1],
                      cur + bOff[j2] + ((uint32_t)ks2 ^ cxB));
#pragma unroll
            for (int im = 0; im < 4; im++)
                ldsm4(a[im][0], a[im][1], a[im][2], a[im][3],
                      cur + aOff[im] + ((uint32_t)ks2 ^ cxA));
#pragma unroll
            for (int im = 0; im < 4; im++)
#pragma unroll
                for (int jn = 0; jn < 4; jn++)
                    mma16816(c[im][jn], a[im], b[jn]);
#pragma unroll
            for (int im = 0; im < 4; im++)
                ldsm4(a[im][0], a[im][1], a[im][2], a[im][3],
                      cur + 16384 + aOff[im] + ((uint32_t)ks2 ^ cxA));
#pragma unroll
            for (int im = 0; im < 4; im++)
#pragma unroll
                for (int jn = 0; jn < 4; jn++)
                    mma16816(c[im][jn], a[im], b[jn]);
        }

        if (i + 1 < nch) {
#pragma unroll
            for (int j = 0; j < 2; j++) { sts16(nxt + aDstH[j], rah[j]); sts16(nxt + aDstL[j], ral[j]); }
#pragma unroll
            for (int j = 0; j < 4; j++) sts16(nxt + bDst[j], rb[j]);
        }
        __syncthreads();
    }

    const int lr = lane >> 2, lc2 = (lane & 3) * 2;
#pragma unroll
    for (int im = 0; im < 4; im++)
#pragma unroll
        for (int jn = 0; jn < 4; jn++) {
            int r0 = bm + wm + im * 16 + lr;
            int col = bn + wn + jn * 8 + lc2;
            if (col < Nstore) {
                *(float2*)&C[(size_t)r0 * Nstore + col] =
                    make_float2(c[im][jn][0], c[im][jn][1]);
                *(float2*)&C[(size_t)(r0 + 8) * Nstore + col] =
                    make_float2(c[im][jn][2], c[im][jn][3]);
            }
        }
}

// ---------------- dt = softplus(raw + bias) ----------------
__global__ void dt_kernel(const float* __restrict__ zx,
                          const float* __restrict__ dt_bias,
                          float* __restrict__ dtb)
{
    int idx = blockIdx.x * blockDim.x + threadIdx.x;
    if (idx >= ROWS * NH) return;
    int h = idx & 63;
    int r = idx >> 6;
    dtb[idx] = softplus_f(zx[(size_t)r * DIP + DIN + CONVD + h] + dt_bias[h]);
}

// ---------------- causal conv1d (width 4) + SiLU ----------------
__global__ void conv_kernel(const float* __restrict__ zx,
                            const float* __restrict__ cw,
                            const float* __restrict__ cb,
                            float* __restrict__ out)
{
    int idx = blockIdx.x * blockDim.x + threadIdx.x;
    if (idx >= ROWS * CONVD) return;
    int ch = idx % CONVD;
    int r  = idx / CONVD;
    int l  = r & (LTOT - 1);
    float acc = cb[ch];
#pragma unroll
    for (int w = 0; w < 4; w++) {
        int lw = l - 3 + w;
        if (lw >= 0)
            acc += zx[(size_t)(r - 3 + w) * DIP + DIN + ch] * cw[ch * 4 + w];
    }
    out[idx] = silu_f(acc);
}

// ---------------- chunked SSD scan (vector-layout operands) ----------------
// Layouts chosen so every inner-loop operand load is a float4:
//   sBt[n][l] (G loop), sB[l][n] (state loop), sCt[n][l] (G+Yo loops),
//   sGt[s][l] (Yd loop), sSt[n][p], sX/sXd[l][p].
#define SSD_FLOATS (128*68*3 + 64*132 + 64*68*3 + 192)
#define SSD_SMEM   (SSD_FLOATS * 4)

__global__ __launch_bounds__(256) void ssd_kernel(
    const float* __restrict__ xbc, const float* __restrict__ dtb,
    const float* __restrict__ A_log, const float* __restrict__ D_param,
    float* __restrict__ y)
{
    extern __shared__ float sm[];
    float* sBt = sm;                  // [128][68] B^T
    float* sCt = sBt + 128 * 68;      // [128][68] C^T
    float* sSt = sCt + 128 * 68;      // [128][68] state [n][p]
    float* sB  = sSt + 128 * 68;      // [64][132] B row-major
    float* sX  = sB  + 64 * 132;      // [64][68]
    float* sXd = sX  + 64 * 68;       // [64][68]
    float* sGt = sXd + 64 * 68;       // [64][68]  G^T[s][l]
    float* sAc = sGt + 64 * 68;       // [64]
    float* sW  = sAc + 64;            // [64]
    float* sdt = sW  + 64;            // [64]

    const int tid = threadIdx.x;
    const int b = blockIdx.x >> 6;
    const int h = blockIdx.x & 63;
    const int tr = tid >> 4, tc = tid & 15;
    const float Ah = -expf(A_log[h]);
    const float Dh = D_param[h];

    for (int i = tid; i < 128 * 68; i += 256) sSt[i] = 0.f;
    __syncthreads();

    for (int c = 0; c < NCHUNK; c++) {
        const int l0 = c * CK;
        const float* xb = xbc + (size_t)(b * LTOT + l0) * CONVD;

        // ---- load B (both layouts), C^T, x ----
#pragma unroll
        for (int i = 0; i < 8; i++) {
            int idx = tid + i * 256;            // 2048 float4 slots
            int l = idx >> 5, n4 = (idx & 31) << 2;
            float4 v = *(const float4*)(xb + (size_t)l * CONVD + DIN + n4);
            sBt[(n4 + 0) * 68 + l] = v.x;
            sBt[(n4 + 1) * 68 + l] = v.y;
            sBt[(n4 + 2) * 68 + l] = v.z;
            sBt[(n4 + 3) * 68 + l] = v.w;
            *(float4*)&sB[l * 132 + n4] = v;
            float4 u = *(const float4*)(xb + (size_t)l * CONVD + DIN + DS + n4);
            sCt[(n4 + 0) * 68 + l] = u.x;
            sCt[(n4 + 1) * 68 + l] = u.y;
            sCt[(n4 + 2) * 68 + l] = u.z;
            sCt[(n4 + 3) * 68 + l] = u.w;
        }
#pragma unroll
        for (int i = 0; i < 4; i++) {
            int idx = tid + i * 256;            // 1024 float4 slots
            int l = idx >> 4, p4 = (idx & 15) << 2;
            *(float4*)&sX[l * 68 + p4] =
                *(const float4*)(xb + (size_t)l * CONVD + h * HD + p4);
        }
        if (tid < CK) sdt[tid] = dtb[(b * LTOT + l0 + tid) * NH + h];
        __syncthreads();

        // ---- cumsum (thread 0) + xd = x * dt ----
        if (tid == 0) {
            float a = 0.f;
            for (int l = 0; l < CK; l++) { a += Ah * sdt[l]; sAc[l] = a; }
            float at = a;
            for (int l = 0; l < CK; l++) sW[l] = expf(at - sAc[l]);
        }
#pragma unroll
        for (int i = 0; i < 4; i++) {
            int idx = tid + i * 256;
            int l = idx >> 4, p4 = (idx & 15) << 2;
            float4 xv = *(float4*)&sX[l * 68 + p4];
            float d = sdt[l];
            *(float4*)&sXd[l * 68 + p4] =
                make_float4(xv.x * d, xv.y * d, xv.z * d, xv.w * d);
        }
        __syncthreads();

        // ---- G[l][s] = (C[l].B[s]) * exp(Ac[l]-Ac[s]), s<=l; store G^T ----
        {
            float g[4][4];                      // [i=l][j=s]
#pragma unroll
            for (int i = 0; i < 4; i++)
#pragma unroll
                for (int j = 0; j < 4; j++) g[i][j] = 0.f;
            for (int nn = 0; nn < DS; nn++) {
                float4 cv = *(float4*)&sCt[nn * 68 + tr * 4];
                float4 bv = *(float4*)&sBt[nn * 68 + tc * 4];
                float cva[4] = {cv.x, cv.y, cv.z, cv.w};
                float bva[4] = {bv.x, bv.y, bv.z, bv.w};
#pragma unroll
                for (int i = 0; i < 4; i++)
#pragma unroll
                    for (int j = 0; j < 4; j++)
                        g[i][j] += cva[i] * bva[j];
            }
#pragma unroll
            for (int j = 0; j < 4; j++) {
                int s = tc * 4 + j;
                float as = sAc[s];
                float o[4];
#pragma unroll
                for (int i = 0; i < 4; i++) {
                    int l = tr * 4 + i;
                    o[i] = (s <= l) ? g[i][j] * expf(sAc[l] - as) : 0.f;
                }
                *(float4*)&sGt[s * 68 + tr * 4] = make_float4(o[0], o[1], o[2], o[3]);
            }
        }
        __syncthreads();

        // ---- Y = G @ xd + exp(Ac[l]) * (C @ state) + D*x ----
        {
            float yd[4][4], yo[4][4];
#pragma unroll
            for (int i = 0; i < 4; i++)
#pragma unroll
                for (int j = 0; j < 4; j++) { yd[i][j] = 0.f; yo[i][j] = 0.f; }
            for (int s = 0; s < CK; s++) {
                float4 gv = *(float4*)&sGt[s * 68 + tr * 4];
                float4 xv = *(float4*)&sXd[s * 68 + tc * 4];
                float gia[4] = {gv.x, gv.y, gv.z, gv.w};
                float xva[4] = {xv.x, xv.y, xv.z, xv.w};
#pragma unroll
                for (int i = 0; i < 4; i++)
#pragma unroll
                    for (int j = 0; j < 4; j++)
                        yd[i][j] += gia[i] * xva[j];
            }
            for (int nn = 0; nn < DS; nn++) {
                float4 cv = *(float4*)&sCt[nn * 68 + tr * 4];
                float4 sv = *(float4*)&sSt[nn * 68 + tc * 4];
                float cva[4] = {cv.x, cv.y, cv.z, cv.w};
                float sva[4] = {sv.x, sv.y, sv.z, sv.w};
#pragma unroll
                for (int i = 0; i < 4; i++)
#pragma unroll
                    for (int j = 0; j < 4; j++)
                        yo[i][j] += cva[i] * sva[j];
            }
#pragma unroll
            for (int i = 0; i < 4; i++) {
                int l = tr * 4 + i;
                float co = expf(sAc[l]);
                float4 xs = *(float4*)&sX[l * 68 + tc * 4];
                float xsa[4] = {xs.x, xs.y, xs.z, xs.w};
                float o[4];
#pragma unroll
                for (int j = 0; j < 4; j++)
                    o[j] = yd[i][j] + co * yo[i][j] + Dh * xsa[j];
                *(float4*)(y + (size_t)(b * LTOT + l0 + l) * DIN + h * HD + tc * 4) =
                    make_float4(o[0], o[1], o[2], o[3]);
            }
        }
        __syncthreads();

        // ---- state[n][p] = exp(Atot)*state + sum_l B[l][n]*w[l]*xd[l][p] ----
        {
            float eT = expf(sAc[CK - 1]);
            float st[8][4];
#pragma unroll
            for (int k = 0; k < 8; k++) {
                float4 v = *(float4*)&sSt[(tr * 8 + k) * 68 + tc * 4];
                st[k][0] = v.x * eT; st[k][1] = v.y * eT;
                st[k][2] = v.z * eT; st[k][3] = v.w * eT;
            }
            for (int l = 0; l < CK; l++) {
                float wl = sW[l];
                float4 xv = *(float4*)&sXd[l * 68 + tc * 4];
                float xw[4] = {xv.x * wl, xv.y * wl, xv.z * wl, xv.w * wl};
                float4 b0 = *(float4*)&sB[l * 132 + tr * 8];
                float4 b1 = *(float4*)&sB[l * 132 + tr * 8 + 4];
                float ba[8] = {b0.x, b0.y, b0.z, b0.w, b1.x, b1.y, b1.z, b1.w};
#pragma unroll
                for (int k = 0; k < 8; k++)
#pragma unroll
                    for (int j = 0; j < 4; j++)
                        st[k][j] += ba[k] * xw[j];
            }
#pragma unroll
            for (int k = 0; k < 8; k++)
                *(float4*)&sSt[(tr * 8 + k) * 68 + tc * 4] =
                    make_float4(st[k][0], st[k][1], st[k][2], st[k][3]);
        }
        __syncthreads();
    }
}

// ---------------- gating + RMSNorm, fused with fp16-split conversion ----
__global__ __launch_bounds__(256) void rms_kernel(
    const float* __restrict__ y, const float* __restrict__ zx,
    const float* __restrict__ nw, __half* __restrict__ A2)
{
    __shared__ float red[256];
    int row = blockIdx.x, tid = threadIdx.x;
    float v[16];
    float ss = 0.f;
#pragma unroll
    for (int i = 0; i < 16; i++) {
        int d = tid + i * 256;
        float yv = y[(size_t)row * DIN + d];
        float zv = zx[(size_t)row * DIP + d];
        float f = yv * silu_f(zv);
        v[i] = f;
        ss += f * f;
    }
    red[tid] = ss;
    __syncthreads();
    for (int s = 128; s > 0; s >>= 1) {
        if (tid < s) red[tid] += red[tid + s];
        __syncthreads();
    }
    float rr = rsqrtf(red[0] / (float)DIN + 1e-5f);
    __half* base = A2 + (size_t)row * (2 * DIN);
#pragma unroll
    for (int i = 0; i < 16; i++) {
        int d = tid + i * 256;
        float x = v[i] * rr * nw[d];
        __half h = __float2half_rn(x);
        __half l = __float2half_rn(x - __half2float(h));
        base[d] = h;
        base[DIN + d] = l;
    }
}

// ---------------- launch ----------------
extern "C" void kernel_launch(void* const* d_in, const int* in_sizes, int n_in,
                              void* d_out, int out_size)
{
    const float* u       = (const float*)d_in[0];
    const float* W_in    = (const float*)d_in[1];
    const float* conv_w  = (const float*)d_in[2];
    const float* conv_b  = (const float*)d_in[3];
    const float* dt_bias = (const float*)d_in[4];
    const float* A_log   = (const float*)d_in[5];
    const float* D_param = (const float*)d_in[6];
    const float* norm_w  = (const float*)d_in[7];
    const float* W_out   = (const float*)d_in[8];
    float* out = (float*)d_out;

    float *zx, *xbc, *dtb, *y;
    __half *hA1, *hB1, *hA2, *hB2;
    cudaGetSymbolAddress((void**)&zx,  g_zx);
    cudaGetSymbolAddress((void**)&xbc, g_xbc);
    cudaGetSymbolAddress((void**)&dtb, g_dt);
    cudaGetSymbolAddress((void**)&y,   g_y);
    cudaGetSymbolAddress((void**)&hA1, g_hA1);
    cudaGetSymbolAddress((void**)&hB1, g_hB1);
    cudaGetSymbolAddress((void**)&hA2, g_hA2);
    cudaGetSymbolAddress((void**)&hB2, g_hB2);

    cudaFuncSetAttribute(ssd_kernel,
                         cudaFuncAttributeMaxDynamicSharedMemorySize, SSD_SMEM);
    cudaFuncSetAttribute(gemm_fp16,
                         cudaFuncAttributeMaxDynamicSharedMemorySize, GG_SMEM);

    // 1) split-fp16 conversion + in-proj GEMM [4096,2048]@[2048,8512]
    convA<<<(int)(((size_t)ROWS * DM) / 256), 256>>>(u, hA1, DM);
    convB<<<dim3(NPAD1 / 32, DM / 32), dim3(32, 32)>>>(W_in, hB1, DM, DIP);
    gemm_fp16<<<dim3(NPAD1 / 256, ROWS / 128), 512, GG_SMEM>>>(hA1, hB1, zx,
                                                               DM, DIP);
    // 2) dt
    dt_kernel<<<(ROWS * NH + 255) / 256, 256>>>(zx, dt_bias, dtb);
    // 3) conv + silu
    conv_kernel<<<(ROWS * CONVD + 255) / 256, 256>>>(zx, conv_w, conv_b, xbc);
    // 4) SSD (vector-layout)
    ssd_kernel<<<NBATCH * NH, 256, SSD_SMEM>>>(xbc, dtb, A_log, D_param, y);
    // 5) gate + RMSNorm (writes fp16 split operand directly)
    rms_kernel<<<ROWS, 256>>>(y, zx, norm_w, hA2);
    // 6) out-proj GEMM [4096,4096]@[4096,2048]
    convB<<<dim3(DM / 32, DIN / 32), dim3(32, 32)>>>(W_out, hB2, DIN, DM);
    gemm_fp16<<<dim3(DM / 256, ROWS / 128), 512, GG_SMEM>>>(hA2, hB2, out,
                                                            DIN, DM);
}

// round 13
// speedup vs baseline: 1.0278x; 1.0278x over previous
#include <cuda_runtime.h>
#include <cuda_fp16.h>
#include <math.h>
#include <stddef.h>
#include <stdint.h>

// ---------------- problem constants ----------------
#define DM     2048
#define DIP    8512
#define NPAD1  8704            // DIP padded to 256 for N-tiles
#define DIN    4096
#define CONVD  4352
#define NH     64
#define HD     64
#define DS     128
#define LTOT   2048
#define NBATCH 2
#define ROWS   (NBATCH*LTOT)   // 4096
#define CK     64
#define NCHUNK (LTOT/CK)

// ---------------- scratch ----------------
__device__ float g_zx [(size_t)ROWS*DIP];
__device__ float g_xbc[(size_t)ROWS*CONVD];
__device__ float g_dt [ROWS*NH];
__device__ float g_y  [(size_t)ROWS*DIN];
// fp16 split A = [Ah|Al] along K (row stride 2K); B single-copy Bh [n][K]
__device__ __half g_hA1[(size_t)ROWS*2*DM];
__device__ __half g_hB1[(size_t)NPAD1*DM];
__device__ __half g_hA2[(size_t)ROWS*2*DIN];
__device__ __half g_hB2[(size_t)DM*DIN];

__device__ __forceinline__ float softplus_f(float x) {
    return (x > 20.f) ? x : log1pf(expf(x));
}
__device__ __forceinline__ float silu_f(float x) {
    return x / (1.f + expf(-x));
}

// ---------------- split-fp16 conversions ----------------
__global__ void convA(const float* __restrict__ X,
                      __half* __restrict__ A2, int K)
{
    size_t idx = (size_t)blockIdx.x * blockDim.x + threadIdx.x;
    int k = (int)(idx % K);
    size_t m = idx / K;
    float x = X[idx];
    __half h = __float2half_rn(x);
    __half l = __float2half_rn(x - __half2float(h));
    __half* base = A2 + m * (size_t)(2 * K);
    base[k] = h; base[K + k] = l;
}

__global__ void convB(const float* __restrict__ W,
                      __half* __restrict__ B2, int K, int N)
{
    __shared__ float t[32][33];
    int n = blockIdx.x * 32 + threadIdx.x;
    int k = blockIdx.y * 32 + threadIdx.y;
    t[threadIdx.y][threadIdx.x] = (n < N) ? W[(size_t)k * N + n] : 0.f;
    __syncthreads();
    int on = blockIdx.x * 32 + threadIdx.y;
    int ok = blockIdx.y * 32 + threadIdx.x;
    B2[(size_t)on * K + ok] = __float2half_rn(t[threadIdx.x][threadIdx.y]);
}

// ---------------- asm helpers ----------------
__device__ __forceinline__ uint32_t smem_u32(const void* p) {
    uint32_t a;
    asm("{ .reg .u64 t; cvta.to.shared.u64 t, %1; cvt.u32.u64 %0, t; }"
        : "=r"(a) : "l"(p));
    return a;
}
__device__ __forceinline__ void ldsm4(uint32_t& r0, uint32_t& r1,
                                      uint32_t& r2, uint32_t& r3, uint32_t a) {
    asm volatile("ldmatrix.sync.aligned.m8n8.x4.shared.b16 {%0,%1,%2,%3}, [%4];"
                 : "=r"(r0), "=r"(r1), "=r"(r2), "=r"(r3) : "r"(a));
}
__device__ __forceinline__ void sts16(uint32_t a, uint4 v) {
    asm volatile("st.shared.v4.b32 [%0], {%1,%2,%3,%4};"
                 :: "r"(a), "r"(v.x), "r"(v.y), "r"(v.z), "r"(v.w) : "memory");
}
__device__ __forceinline__ void mma16816(float* d, const uint32_t* a,
                                         const uint32_t* b) {
    asm volatile(
        "mma.sync.aligned.m16n8k16.row.col.f32.f16.f16.f32 "
        "{%0,%1,%2,%3}, {%4,%5,%6,%7}, {%8,%9}, {%0,%1,%2,%3};\n"
        : "+f"(d[0]), "+f"(d[1]), "+f"(d[2]), "+f"(d[3])
        : "r"(a[0]), "r"(a[1]), "r"(a[2]), "r"(a[3]),
          "r"(b[0]), "r"(b[1]));
}
__device__ __forceinline__ uint32_t swz128(uint32_t off) {
    return off ^ ((off >> 3) & 0x70);
}

// ---------------- fp16 GEMM (shared-B split): C = (Ah+Al) @ Bh^T ----------
#define GG_STAGE 65536
#define GG_SMEM  (1024 + 2 * GG_STAGE)

__global__ __launch_bounds__(512) void gemm_fp16(
    const __half* __restrict__ A, const __half* __restrict__ B,
    float* __restrict__ C, int K, int Nstore)
{
    extern __shared__ char smem[];
    const uint32_t sb = (smem_u32(smem) + 1023u) & ~1023u;
    const int tid = threadIdx.x;
    const int wid = tid >> 5, lane = tid & 31;
    const int bm = blockIdx.y * 128, bn = blockIdx.x * 256;
    const int wm = (wid & 1) * 64, wn = (wid >> 1) * 32;
    const int nch = K >> 6;

    const uint4* aSrcH[2];
    const uint4* aSrcL[2];
    const uint4* bSrc[4];
    uint32_t aDstH[2], aDstL[2], bDst[4];
#pragma unroll
    for (int j = 0; j < 2; j++) {
        int u = tid + 512 * j;
        int row = u >> 3, seg = u & 7;
        const __half* pa = A + (size_t)(bm + row) * (2 * K) + seg * 8;
        aSrcH[j] = (const uint4*)pa;
        aSrcL[j] = (const uint4*)(pa + K);
        uint32_t sw = swz128(row * 128 + seg * 16);
        aDstH[j] = sw;
        aDstL[j] = sw + 16384;
    }
#pragma unroll
    for (int j = 0; j < 4; j++) {
        int u = tid + 512 * j;
        int row = u >> 3, seg = u & 7;
        bSrc[j] = (const uint4*)(B + (size_t)(bn + row) * K + seg * 8);
        bDst[j] = 32768 + swz128(row * 128 + seg * 16);
    }

    const uint32_t cxA = (((lane & 7) ^ (lane >> 4)) << 4);
    uint32_t aOff[4];
#pragma unroll
    for (int im = 0; im < 4; im++)
        aOff[im] = (wm + im * 16 + (lane & 15)) * 128;
    const uint32_t cxB = (((lane & 7) ^ ((lane >> 3) & 1)) << 4);
    uint32_t bOff[2];
#pragma unroll
    for (int j2 = 0; j2 < 2; j2++)
        bOff[j2] = 32768 + (wn + j2 * 16 + (lane >> 4) * 8 + (lane & 7)) * 128;

    float c[4][4][4];
#pragma unroll
    for (int i = 0; i < 4; i++)
#pragma unroll
        for (int j = 0; j < 4; j++)
#pragma unroll
            for (int r = 0; r < 4; r++) c[i][j][r] = 0.f;

    uint4 rah[2], ral[2], rb[4];
#pragma unroll
    for (int j = 0; j < 2; j++) { rah[j] = aSrcH[j][0]; ral[j] = aSrcL[j][0]; }
#pragma unroll
    for (int j = 0; j < 4; j++) rb[j] = bSrc[j][0];
#pragma unroll
    for (int j = 0; j < 2; j++) { sts16(sb + aDstH[j], rah[j]); sts16(sb + aDstL[j], ral[j]); }
#pragma unroll
    for (int j = 0; j < 4; j++) sts16(sb + bDst[j], rb[j]);
    __syncthreads();

    for (int i = 0; i < nch; i++) {
        const uint32_t cur = sb + (uint32_t)(i & 1) * GG_STAGE;
        const uint32_t nxt = sb + (uint32_t)((i + 1) & 1) * GG_STAGE;

        if (i + 1 < nch) {
            size_t ko = (size_t)(i + 1) * 8;
#pragma unroll
            for (int j = 0; j < 2; j++) { rah[j] = aSrcH[j][ko]; ral[j] = aSrcL[j][ko]; }
#pragma unroll
            for (int j = 0; j < 4; j++) rb[j] = bSrc[j][ko];
        }

#pragma unroll
        for (int ks2 = 0; ks2 < 128; ks2 += 32) {
            uint32_t a[4][4], b[4][2];
#pragma unroll
            for (int j2 = 0; j2 < 2; j2++)
                ldsm4(b[2 * j2][0], b[2 * j2][1], b[2 * j2 + 1][0], b[2 * j2 + 1][1],
                      cur + bOff[j2] + ((uint32_t)ks2 ^ cxB));
#pragma unroll
            for (int im = 0; im < 4; im++)
                ldsm4(a[im][0], a[im][1], a[im][2], a[im][3],
                      cur + aOff[im] + ((uint32_t)ks2 ^ cxA));
#pragma unroll
            for (int im = 0; im < 4; im++)
#pragma unroll
                for (int jn = 0; jn < 4; jn++)
                    mma16816(c[im][jn], a[im], b[jn]);
#pragma unroll
            for (int im = 0; im < 4; im++)
                ldsm4(a[im][0], a[im][1], a[im][2], a[im][3],
                      cur + 16384 + aOff[im] + ((uint32_t)ks2 ^ cxA));
#pragma unroll
            for (int im = 0; im < 4; im++)
#pragma unroll
                for (int jn = 0; jn < 4; jn++)
                    mma16816(c[im][jn], a[im], b[jn]);
        }

        if (i + 1 < nch) {
#pragma unroll
            for (int j = 0; j < 2; j++) { sts16(nxt + aDstH[j], rah[j]); sts16(nxt + aDstL[j], ral[j]); }
#pragma unroll
            for (int j = 0; j < 4; j++) sts16(nxt + bDst[j], rb[j]);
        }
        __syncthreads();
    }

    const int lr = lane >> 2, lc2 = (lane & 3) * 2;
#pragma unroll
    for (int im = 0; im < 4; im++)
#pragma unroll
        for (int jn = 0; jn < 4; jn++) {
            int r0 = bm + wm + im * 16 + lr;
            int col = bn + wn + jn * 8 + lc2;
            if (col < Nstore) {
                *(float2*)&C[(size_t)r0 * Nstore + col] =
                    make_float2(c[im][jn][0], c[im][jn][1]);
                *(float2*)&C[(size_t)(r0 + 8) * Nstore + col] =
                    make_float2(c[im][jn][2], c[im][jn][3]);
            }
        }
}

// ---------------- dt = softplus(raw + bias) ----------------
__global__ void dt_kernel(const float* __restrict__ zx,
                          const float* __restrict__ dt_bias,
                          float* __restrict__ dtb)
{
    int idx = blockIdx.x * blockDim.x + threadIdx.x;
    if (idx >= ROWS * NH) return;
    int h = idx & 63;
    int r = idx >> 6;
    dtb[idx] = softplus_f(zx[(size_t)r * DIP + DIN + CONVD + h] + dt_bias[h]);
}

// ---------------- causal conv1d (width 4) + SiLU ----------------
__global__ void conv_kernel(const float* __restrict__ zx,
                            const float* __restrict__ cw,
                            const float* __restrict__ cb,
                            float* __restrict__ out)
{
    int idx = blockIdx.x * blockDim.x + threadIdx.x;
    if (idx >= ROWS * CONVD) return;
    int ch = idx % CONVD;
    int r  = idx / CONVD;
    int l  = r & (LTOT - 1);
    float acc = cb[ch];
#pragma unroll
    for (int w = 0; w < 4; w++) {
        int lw = l - 3 + w;
        if (lw >= 0)
            acc += zx[(size_t)(r - 3 + w) * DIP + DIN + ch] * cw[ch * 4 + w];
    }
    out[idx] = silu_f(acc);
}

// ---------------- chunked SSD scan: tensor-core G/Yo ----------------
// fp32: sBt[128][68] | sSt[128][68] | sXd[64][68] | sG[64][68] | sYo[64][68]
//       sAc[64] sW[64] sdt[64]
// fp16 (1024-aligned): Ch(16KB) Cl(16KB) BSh(32KB) BSl(32KB)
//   C regions: [2 k-chunks][64 rows l][128B]; BS: [2 k-chunks][128 rows][128B]
//   BS rows 0..63 = B tokens (s), rows 64..127 = S^T (p).
#define SSD_F32_FLOATS (8704*2 + 4352*3 + 192)
#define SSD_H_OFF      123904            // >= SSD_F32_FLOATS*4, 1024-mult
#define SSD_SMEM       (1024 + SSD_H_OFF + 98304)
#define CH_OFF   0
#define CL_OFF   16384
#define BSH_OFF  32768
#define BSL_OFF  65536

__global__ __launch_bounds__(256) void ssd_kernel(
    const float* __restrict__ xbc, const float* __restrict__ dtb,
    const float* __restrict__ A_log, const float* __restrict__ D_param,
    float* __restrict__ y)
{
    extern __shared__ char smraw[];
    char* base = (char*)((((uintptr_t)smraw) + 1023) & ~(uintptr_t)1023);
    const uint32_t sbase = (smem_u32(smraw) + 1023u) & ~1023u;
    float* sBt = (float*)base;            // [128][68]
    float* sSt = sBt + 8704;              // [128][68]
    float* sXd = sSt + 8704;              // [64][68]  x then x*dt
    float* sG  = sXd + 4352;              // [64][68]
    float* sYo = sG  + 4352;              // [64][68]
    float* sAc = sYo + 4352;
    float* sW  = sAc + 64;
    float* sdt = sW  + 64;
    char*  hbyte = base + SSD_H_OFF;
    const uint32_t hb = sbase + SSD_H_OFF;

    const int tid = threadIdx.x;
    const int b = blockIdx.x >> 6;
    const int h = blockIdx.x & 63;
    const int tr = tid >> 4, tc = tid & 15;
    const int w = tid >> 5, lane = tid & 31;
    const float Ah = -expf(A_log[h]);
    const float Dh = D_param[h];

    // zero state + BS buffers (S rows must start 0)
    for (int i = tid; i < 8704; i += 256) sSt[i] = 0.f;
    for (int i = tid; i < 16384; i += 256) ((uint32_t*)(hbyte + BSH_OFF))[i] = 0;
    __syncthreads();

    // mma constants
    const int mm = (w & 3) * 16;
    const int hh = w >> 2;
    const uint32_t aoff = (uint32_t)(mm + (lane & 15)) * 128;
    const uint32_t cxA = (((lane & 7) ^ (lane >> 4)) << 4);
    const uint32_t cxB = (((lane & 7) ^ ((lane >> 3) & 1)) << 4);
    uint32_t boff[4];
#pragma unroll
    for (int j2 = 0; j2 < 4; j2++)
        boff[j2] = (uint32_t)(hh * 64 + j2 * 16 + ((lane >> 4) * 8) + (lane & 7)) * 128;
    const int lr = lane >> 2, lc2 = (lane & 3) * 2;

    for (int c = 0; c < NCHUNK; c++) {
        const int l0 = c * CK;
        const float* xb = xbc + (size_t)(b * LTOT + l0) * CONVD;

        // ---- load B (sBt fp32 + BS fp16 h/l), C (Ch/Cl fp16), x ----
#pragma unroll
        for (int i = 0; i < 8; i++) {
            int idx = tid + i * 256;
            int l = idx >> 5, n4 = (idx & 31) << 2;
            int chnk = (n4 >= 64) ? 1 : 0;
            int colb = (n4 & 63) * 2;
            uint32_t rowsw = swz128((uint32_t)(l * 128 + (colb & ~15))) + (colb & 8);

            float4 v = *(const float4*)(xb + (size_t)l * CONVD + DIN + n4);
            sBt[(n4 + 0) * 68 + l] = v.x;
            sBt[(n4 + 1) * 68 + l] = v.y;
            sBt[(n4 + 2) * 68 + l] = v.z;
            sBt[(n4 + 3) * 68 + l] = v.w;
            {
                __half hx = __float2half_rn(v.x), hy = __float2half_rn(v.y);
                __half hz = __float2half_rn(v.z), hw = __float2half_rn(v.w);
                char* p = hbyte + BSH_OFF + chnk * 16384 + rowsw;
                *(__half2*)(p)     = __halves2half2(hx, hy);
                *(__half2*)(p + 4) = __halves2half2(hz, hw);
                __half lx = __float2half_rn(v.x - __half2float(hx));
                __half ly = __float2half_rn(v.y - __half2float(hy));
                __half lz = __float2half_rn(v.z - __half2float(hz));
                __half lw = __float2half_rn(v.w - __half2float(hw));
                char* q = hbyte + BSL_OFF + chnk * 16384 + rowsw;
                *(__half2*)(q)     = __halves2half2(lx, ly);
                *(__half2*)(q + 4) = __halves2half2(lz, lw);
            }
            float4 u = *(const float4*)(xb + (size_t)l * CONVD + DIN + DS + n4);
            {
                __half hx = __float2half_rn(u.x), hy = __float2half_rn(u.y);
                __half hz = __float2half_rn(u.z), hw = __float2half_rn(u.w);
                char* p = hbyte + CH_OFF + chnk * 8192 + rowsw;
                *(__half2*)(p)     = __halves2half2(hx, hy);
                *(__half2*)(p + 4) = __halves2half2(hz, hw);
                __half lx = __float2half_rn(u.x - __half2float(hx));
                __half ly = __float2half_rn(u.y - __half2float(hy));
                __half lz = __float2half_rn(u.z - __half2float(hz));
                __half lw = __float2half_rn(u.w - __half2float(hw));
                char* q = hbyte + CL_OFF + chnk * 8192 + rowsw;
                *(__half2*)(q)     = __halves2half2(lx, ly);
                *(__half2*)(q + 4) = __halves2half2(lz, lw);
            }
        }
#pragma unroll
        for (int i = 0; i < 4; i++) {
            int idx = tid + i * 256;
            int l = idx >> 4, p4 = (idx & 15) << 2;
            *(float4*)&sXd[l * 68 + p4] =
                *(const float4*)(xb + (size_t)l * CONVD + h * HD + p4);
        }
        if (tid < CK) sdt[tid] = dtb[(b * LTOT + l0 + tid) * NH + h];
        __syncthreads();

        // ---- cumsum (thread 0); xd = x * dt (in place) ----
        if (tid == 0) {
            float a = 0.f;
            for (int l = 0; l < CK; l++) { a += Ah * sdt[l]; sAc[l] = a; }
            float at = a;
            for (int l = 0; l < CK; l++) sW[l] = expf(at - sAc[l]);
        }
#pragma unroll
        for (int i = 0; i < 4; i++) {
            int idx = tid + i * 256;
            int l = idx >> 4, p4 = (idx & 15) << 2;
            float4 xv = *(float4*)&sXd[l * 68 + p4];
            float d = sdt[l];
            *(float4*)&sXd[l * 68 + p4] =
                make_float4(xv.x * d, xv.y * d, xv.z * d, xv.w * d);
        }
        __syncthreads();

        // ---- mma: [G0 | Yo] = C * [B | S^T]^T  (3-pass split) ----
        {
            float acc[8][4];
#pragma unroll
            for (int jn = 0; jn < 8; jn++)
#pragma unroll
                for (int r = 0; r < 4; r++) acc[jn][r] = 0.f;
#pragma unroll
            for (int pass = 0; pass < 3; pass++) {
                uint32_t aB = hb + ((pass == 1) ? CL_OFF : CH_OFF);
                uint32_t bB = hb + ((pass == 2) ? BSL_OFF : BSH_OFF);
#pragma unroll
                for (int kc = 0; kc < 2; kc++) {
                    uint32_t aC = aB + kc * 8192;
                    uint32_t bC = bB + kc * 16384;
#pragma unroll
                    for (int ks2 = 0; ks2 < 128; ks2 += 32) {
                        uint32_t a4[4], bf[8][2];
                        ldsm4(a4[0], a4[1], a4[2], a4[3],
                              aC + aoff + ((uint32_t)ks2 ^ cxA));
#pragma unroll
                        for (int j2 = 0; j2 < 4; j2++)
                            ldsm4(bf[2 * j2][0], bf[2 * j2][1],
                                  bf[2 * j2 + 1][0], bf[2 * j2 + 1][1],
                                  bC + boff[j2] + ((uint32_t)ks2 ^ cxB));
#pragma unroll
                        for (int jn = 0; jn < 8; jn++)
                            mma16816(acc[jn], a4, bf[jn]);
                    }
                }
            }
            // epilogue: hh=0 -> G with decay mask; hh=1 -> raw Yo
            if (hh == 0) {
#pragma unroll
                for (int r = 0; r < 2; r++) {
                    int l = mm + lr + r * 8;
                    float al = sAc[l];
#pragma unroll
                    for (int jn = 0; jn < 8; jn++) {
                        int s0 = jn * 8 + lc2;
                        float v0 = (s0 <= l)
                            ? acc[jn][r * 2 + 0] * expf(al - sAc[s0]) : 0.f;
                        float v1 = (s0 + 1 <= l)
                            ? acc[jn][r * 2 + 1] * expf(al - sAc[s0 + 1]) : 0.f;
                        *(float2*)&sG[l * 68 + s0] = make_float2(v0, v1);
                    }
                }
            } else {
#pragma unroll
                for (int r = 0; r < 2; r++) {
                    int l = mm + lr + r * 8;
#pragma unroll
                    for (int jn = 0; jn < 8; jn++) {
                        int p0 = jn * 8 + lc2;
                        *(float2*)&sYo[l * 68 + p0] =
                            make_float2(acc[jn][r * 2 + 0], acc[jn][r * 2 + 1]);
                    }
                }
            }
        }
        __syncthreads();

        // ---- Y = G @ xd + exp(Ac[l])*Yo + D*x  (x = xd/dt) ----
        {
            float yd[4][4];
#pragma unroll
            for (int i = 0; i < 4; i++)
#pragma unroll
                for (int j = 0; j < 4; j++) yd[i][j] = 0.f;
            for (int s = 0; s < CK; s++) {
                float gi[4];
#pragma unroll
                for (int i = 0; i < 4; i++) gi[i] = sG[(tr * 4 + i) * 68 + s];
                float4 xv4 = *(float4*)&sXd[s * 68 + tc * 4];
                float xva[4] = {xv4.x, xv4.y, xv4.z, xv4.w};
#pragma unroll
                for (int i = 0; i < 4; i++)
#pragma unroll
                    for (int j = 0; j < 4; j++)
                        yd[i][j] += gi[i] * xva[j];
            }
#pragma unroll
            for (int i = 0; i < 4; i++) {
                int l = tr * 4 + i;
                float co = expf(sAc[l]);
                float fx = Dh / sdt[l];
                float4 yo4 = *(float4*)&sYo[l * 68 + tc * 4];
                float4 xd4 = *(float4*)&sXd[l * 68 + tc * 4];
                float o0 = yd[i][0] + co * yo4.x + fx * xd4.x;
                float o1 = yd[i][1] + co * yo4.y + fx * xd4.y;
                float o2 = yd[i][2] + co * yo4.z + fx * xd4.z;
                float o3 = yd[i][3] + co * yo4.w + fx * xd4.w;
                *(float4*)(y + (size_t)(b * LTOT + l0 + l) * DIN + h * HD + tc * 4) =
                    make_float4(o0, o1, o2, o3);
            }
        }
        __syncthreads();

        // ---- state update + S^T fp16 export ----
        {
            float eT = expf(sAc[CK - 1]);
            float st[8][4];
#pragma unroll
            for (int k = 0; k < 8; k++) {
                float4 v = *(float4*)&sSt[(tr * 8 + k) * 68 + tc * 4];
                st[k][0] = v.x * eT; st[k][1] = v.y * eT;
                st[k][2] = v.z * eT; st[k][3] = v.w * eT;
            }
            for (int l = 0; l < CK; l++) {
                float wl = sW[l];
                float4 xv4 = *(float4*)&sXd[l * 68 + tc * 4];
                float xv[4] = {xv4.x, xv4.y, xv4.z, xv4.w};
#pragma unroll
                for (int k = 0; k < 8; k++) {
                    float bw = sBt[(tr * 8 + k) * 68 + l] * wl;
#pragma unroll
                    for (int j = 0; j < 4; j++)
                        st[k][j] += bw * xv[j];
                }
            }
#pragma unroll
            for (int k = 0; k < 8; k++)
                *(float4*)&sSt[(tr * 8 + k) * 68 + tc * 4] =
                    make_float4(st[k][0], st[k][1], st[k][2], st[k][3]);

            // S^T rows 64+p: thread has n = tr*8..tr*8+7 (contig), p = tc*4+j
            int chnk = (tr >= 8) ? 1 : 0;
            int seg16 = (tr & 7) * 16;
#pragma unroll
            for (int j = 0; j < 4; j++) {
                int p = tc * 4 + j;
                uint32_t rowsw = swz128((uint32_t)((64 + p) * 128 + seg16));
                char* ph = hbyte + BSH_OFF + chnk * 16384 + rowsw;
                char* pl = hbyte + BSL_OFF + chnk * 16384 + rowsw;
#pragma unroll
                for (int k2 = 0; k2 < 4; k2++) {
                    float v0 = st[k2 * 2 + 0][j], v1 = st[k2 * 2 + 1][j];
                    __half h0 = __float2half_rn(v0), h1 = __float2half_rn(v1);
                    *(__half2*)(ph + k2 * 4) = __halves2half2(h0, h1);
                    *(__half2*)(pl + k2 * 4) = __halves2half2(
                        __float2half_rn(v0 - __half2float(h0)),
                        __float2half_rn(v1 - __half2float(h1)));
                }
            }
        }
        __syncthreads();
    }
}

// ---------------- gating + RMSNorm, fused with fp16-split conversion ----
__global__ __launch_bounds__(256) void rms_kernel(
    const float* __restrict__ y, const float* __restrict__ zx,
    const float* __restrict__ nw, __half* __restrict__ A2)
{
    __shared__ float red[256];
    int row = blockIdx.x, tid = threadIdx.x;
    float v[16];
    float ss = 0.f;
#pragma unroll
    for (int i = 0; i < 16; i++) {
        int d = tid + i * 256;
        float yv = y[(size_t)row * DIN + d];
        float zv = zx[(size_t)row * DIP + d];
        float f = yv * silu_f(zv);
        v[i] = f;
        ss += f * f;
    }
    red[tid] = ss;
    __syncthreads();
    for (int s = 128; s > 0; s >>= 1) {
        if (tid < s) red[tid] += red[tid + s];
        __syncthreads();
    }
    float rr = rsqrtf(red[0] / (float)DIN + 1e-5f);
    __half* base = A2 + (size_t)row * (2 * DIN);
#pragma unroll
    for (int i = 0; i < 16; i++) {
        int d = tid + i * 256;
        float x = v[i] * rr * nw[d];
        __half h = __float2half_rn(x);
        __half l = __float2half_rn(x - __half2float(h));
        base[d] = h;
        base[DIN + d] = l;
    }
}

// ---------------- launch ----------------
extern "C" void kernel_launch(void* const* d_in, const int* in_sizes, int n_in,
                              void* d_out, int out_size)
{
    const float* u       = (const float*)d_in[0];
    const float* W_in    = (const float*)d_in[1];
    const float* conv_w  = (const float*)d_in[2];
    const float* conv_b  = (const float*)d_in[3];
    const float* dt_bias = (const float*)d_in[4];
    const float* A_log   = (const float*)d_in[5];
    const float* D_param = (const float*)d_in[6];
    const float* norm_w  = (const float*)d_in[7];
    const float* W_out   = (const float*)d_in[8];
    float* out = (float*)d_out;

    float *zx, *xbc, *dtb, *y;
    __half *hA1, *hB1, *hA2, *hB2;
    cudaGetSymbolAddress((void**)&zx,  g_zx);
    cudaGetSymbolAddress((void**)&xbc, g_xbc);
    cudaGetSymbolAddress((void**)&dtb, g_dt);
    cudaGetSymbolAddress((void**)&y,   g_y);
    cudaGetSymbolAddress((void**)&hA1, g_hA1);
    cudaGetSymbolAddress((void**)&hB1, g_hB1);
    cudaGetSymbolAddress((void**)&hA2, g_hA2);
    cudaGetSymbolAddress((void**)&hB2, g_hB2);

    cudaFuncSetAttribute(ssd_kernel,
                         cudaFuncAttributeMaxDynamicSharedMemorySize, SSD_SMEM);
    cudaFuncSetAttribute(gemm_fp16,
                         cudaFuncAttributeMaxDynamicSharedMemorySize, GG_SMEM);

    // 1) split-fp16 conversion + in-proj GEMM [4096,2048]@[2048,8512]
    convA<<<(int)(((size_t)ROWS * DM) / 256), 256>>>(u, hA1, DM);
    convB<<<dim3(NPAD1 / 32, DM / 32), dim3(32, 32)>>>(W_in, hB1, DM, DIP);
    gemm_fp16<<<dim3(NPAD1 / 256, ROWS / 128), 512, GG_SMEM>>>(hA1, hB1, zx,
                                                               DM, DIP);
    // 2) dt
    dt_kernel<<<(ROWS * NH + 255) / 256, 256>>>(zx, dt_bias, dtb);
    // 3) conv + silu
    conv_kernel<<<(ROWS * CONVD + 255) / 256, 256>>>(zx, conv_w, conv_b, xbc);
    // 4) SSD (tensor-core G/Yo)
    ssd_kernel<<<NBATCH * NH, 256, SSD_SMEM>>>(xbc, dtb, A_log, D_param, y);
    // 5) gate + RMSNorm (writes fp16 split operand directly)
    rms_kernel<<<ROWS, 256>>>(y, zx, norm_w, hA2);
    // 6) out-proj GEMM [4096,4096]@[4096,2048]
    convB<<<dim3(DM / 32, DIN / 32), dim3(32, 32)>>>(W_out, hB2, DIN, DM);
    gemm_fp16<<<dim3(DM / 256, ROWS / 128), 512, GG_SMEM>>>(hA2, hB2, out,
                                                            DIN, DM);
}

// round 15
// speedup vs baseline: 1.0567x; 1.0280x over previous
#include <cuda_runtime.h>
#include <cuda_fp16.h>
#include <math.h>
#include <stddef.h>
#include <stdint.h>

// ---------------- problem constants ----------------
#define DM     2048
#define DIP    8512
#define NPAD1  8704            // DIP padded to 256 for N-tiles
#define DIN    4096
#define CONVD  4352
#define NH     64
#define HD     64
#define DS     128
#define LTOT   2048
#define NBATCH 2
#define ROWS   (NBATCH*LTOT)   // 4096
#define CK     64
#define NCHUNK (LTOT/CK)

// ---------------- scratch ----------------
__device__ float g_zx [(size_t)ROWS*DIP];
__device__ float g_xbc[(size_t)ROWS*CONVD];
__device__ float g_dt [ROWS*NH];
__device__ float g_y  [(size_t)ROWS*DIN];
// fp16 split A = [Ah|Al] along K (row stride 2K); B single-copy Bh [n][K]
__device__ __half g_hA1[(size_t)ROWS*2*DM];
__device__ __half g_hB1[(size_t)NPAD1*DM];
__device__ __half g_hA2[(size_t)ROWS*2*DIN];
__device__ __half g_hB2[(size_t)DM*DIN];

__device__ __forceinline__ float softplus_f(float x) {
    return (x > 20.f) ? x : log1pf(expf(x));
}
__device__ __forceinline__ float silu_f(float x) {
    return x / (1.f + expf(-x));
}

// ---------------- split-fp16 conversions ----------------
__global__ void convA(const float* __restrict__ X,
                      __half* __restrict__ A2, int K)
{
    size_t idx = (size_t)blockIdx.x * blockDim.x + threadIdx.x;
    int k = (int)(idx % K);
    size_t m = idx / K;
    float x = X[idx];
    __half h = __float2half_rn(x);
    __half l = __float2half_rn(x - __half2float(h));
    __half* base = A2 + m * (size_t)(2 * K);
    base[k] = h; base[K + k] = l;
}

__global__ void convB(const float* __restrict__ W,
                      __half* __restrict__ B2, int K, int N)
{
    __shared__ float t[32][33];
    int n = blockIdx.x * 32 + threadIdx.x;
    int k = blockIdx.y * 32 + threadIdx.y;
    t[threadIdx.y][threadIdx.x] = (n < N) ? W[(size_t)k * N + n] : 0.f;
    __syncthreads();
    int on = blockIdx.x * 32 + threadIdx.y;
    int ok = blockIdx.y * 32 + threadIdx.x;
    B2[(size_t)on * K + ok] = __float2half_rn(t[threadIdx.x][threadIdx.y]);
}

// ---------------- asm helpers ----------------
__device__ __forceinline__ uint32_t smem_u32(const void* p) {
    uint32_t a;
    asm("{ .reg .u64 t; cvta.to.shared.u64 t, %1; cvt.u32.u64 %0, t; }"
        : "=r"(a) : "l"(p));
    return a;
}
__device__ __forceinline__ void ldsm4(uint32_t& r0, uint32_t& r1,
                                      uint32_t& r2, uint32_t& r3, uint32_t a) {
    asm volatile("ldmatrix.sync.aligned.m8n8.x4.shared.b16 {%0,%1,%2,%3}, [%4];"
                 : "=r"(r0), "=r"(r1), "=r"(r2), "=r"(r3) : "r"(a));
}
__device__ __forceinline__ void sts16(uint32_t a, uint4 v) {
    asm volatile("st.shared.v4.b32 [%0], {%1,%2,%3,%4};"
                 :: "r"(a), "r"(v.x), "r"(v.y), "r"(v.z), "r"(v.w) : "memory");
}
__device__ __forceinline__ void mma16816(float* d, const uint32_t* a,
                                         const uint32_t* b) {
    asm volatile(
        "mma.sync.aligned.m16n8k16.row.col.f32.f16.f16.f32 "
        "{%0,%1,%2,%3}, {%4,%5,%6,%7}, {%8,%9}, {%0,%1,%2,%3};\n"
        : "+f"(d[0]), "+f"(d[1]), "+f"(d[2]), "+f"(d[3])
        : "r"(a[0]), "r"(a[1]), "r"(a[2]), "r"(a[3]),
          "r"(b[0]), "r"(b[1]));
}
__device__ __forceinline__ uint32_t swz128(uint32_t off) {
    return off ^ ((off >> 3) & 0x70);
}

// ---------------- fp16 GEMM (shared-B split): C = (Ah+Al) @ Bh^T ----------
#define GG_STAGE 65536
#define GG_SMEM  (1024 + 2 * GG_STAGE)

__global__ __launch_bounds__(512) void gemm_fp16(
    const __half* __restrict__ A, const __half* __restrict__ B,
    float* __restrict__ C, int K, int Nstore)
{
    extern __shared__ char smem[];
    const uint32_t sb = (smem_u32(smem) + 1023u) & ~1023u;
    const int tid = threadIdx.x;
    const int wid = tid >> 5, lane = tid & 31;
    const int bm = blockIdx.y * 128, bn = blockIdx.x * 256;
    const int wm = (wid & 1) * 64, wn = (wid >> 1) * 32;
    const int nch = K >> 6;

    const uint4* aSrcH[2];
    const uint4* aSrcL[2];
    const uint4* bSrc[4];
    uint32_t aDstH[2], aDstL[2], bDst[4];
#pragma unroll
    for (int j = 0; j < 2; j++) {
        int u = tid + 512 * j;
        int row = u >> 3, seg = u & 7;
        const __half* pa = A + (size_t)(bm + row) * (2 * K) + seg * 8;
        aSrcH[j] = (const uint4*)pa;
        aSrcL[j] = (const uint4*)(pa + K);
        uint32_t sw = swz128(row * 128 + seg * 16);
        aDstH[j] = sw;
        aDstL[j] = sw + 16384;
    }
#pragma unroll
    for (int j = 0; j < 4; j++) {
        int u = tid + 512 * j;
        int row = u >> 3, seg = u & 7;
        bSrc[j] = (const uint4*)(B + (size_t)(bn + row) * K + seg * 8);
        bDst[j] = 32768 + swz128(row * 128 + seg * 16);
    }

    const uint32_t cxA = (((lane & 7) ^ (lane >> 4)) << 4);
    uint32_t aOff[4];
#pragma unroll
    for (int im = 0; im < 4; im++)
        aOff[im] = (wm + im * 16 + (lane & 15)) * 128;
    const uint32_t cxB = (((lane & 7) ^ ((lane >> 3) & 1)) << 4);
    uint32_t bOff[2];
#pragma unroll
    for (int j2 = 0; j2 < 2; j2++)
        bOff[j2] = 32768 + (wn + j2 * 16 + (lane >> 4) * 8 + (lane & 7)) * 128;

    float c[4][4][4];
#pragma unroll
    for (int i = 0; i < 4; i++)
#pragma unroll
        for (int j = 0; j < 4; j++)
#pragma unroll
            for (int r = 0; r < 4; r++) c[i][j][r] = 0.f;

    uint4 rah[2], ral[2], rb[4];
#pragma unroll
    for (int j = 0; j < 2; j++) { rah[j] = aSrcH[j][0]; ral[j] = aSrcL[j][0]; }
#pragma unroll
    for (int j = 0; j < 4; j++) rb[j] = bSrc[j][0];
#pragma unroll
    for (int j = 0; j < 2; j++) { sts16(sb + aDstH[j], rah[j]); sts16(sb + aDstL[j], ral[j]); }
#pragma unroll
    for (int j = 0; j < 4; j++) sts16(sb + bDst[j], rb[j]);
    __syncthreads();

    for (int i = 0; i < nch; i++) {
        const uint32_t cur = sb + (uint32_t)(i & 1) * GG_STAGE;
        const uint32_t nxt = sb + (uint32_t)((i + 1) & 1) * GG_STAGE;

        if (i + 1 < nch) {
            size_t ko = (size_t)(i + 1) * 8;
#pragma unroll
            for (int j = 0; j < 2; j++) { rah[j] = aSrcH[j][ko]; ral[j] = aSrcL[j][ko]; }
#pragma unroll
            for (int j = 0; j < 4; j++) rb[j] = bSrc[j][ko];
        }

#pragma unroll
        for (int ks2 = 0; ks2 < 128; ks2 += 32) {
            uint32_t a[4][4], b[4][2];
#pragma unroll
            for (int j2 = 0; j2 < 2; j2++)
                ldsm4(b[2 * j2][0], b[2 * j2][1], b[2 * j2 + 1][0], b[2 * j2 + 1][1],
                      cur + bOff[j2] + ((uint32_t)ks2 ^ cxB));
#pragma unroll
            for (int im = 0; im < 4; im++)
                ldsm4(a[im][0], a[im][1], a[im][2], a[im][3],
                      cur + aOff[im] + ((uint32_t)ks2 ^ cxA));
#pragma unroll
            for (int im = 0; im < 4; im++)
#pragma unroll
                for (int jn = 0; jn < 4; jn++)
                    mma16816(c[im][jn], a[im], b[jn]);
#pragma unroll
            for (int im = 0; im < 4; im++)
                ldsm4(a[im][0], a[im][1], a[im][2], a[im][3],
                      cur + 16384 + aOff[im] + ((uint32_t)ks2 ^ cxA));
#pragma unroll
            for (int im = 0; im < 4; im++)
#pragma unroll
                for (int jn = 0; jn < 4; jn++)
                    mma16816(c[im][jn], a[im], b[jn]);
        }

        if (i + 1 < nch) {
#pragma unroll
            for (int j = 0; j < 2; j++) { sts16(nxt + aDstH[j], rah[j]); sts16(nxt + aDstL[j], ral[j]); }
#pragma unroll
            for (int j = 0; j < 4; j++) sts16(nxt + bDst[j], rb[j]);
        }
        __syncthreads();
    }

    const int lr = lane >> 2, lc2 = (lane & 3) * 2;
#pragma unroll
    for (int im = 0; im < 4; im++)
#pragma unroll
        for (int jn = 0; jn < 4; jn++) {
            int r0 = bm + wm + im * 16 + lr;
            int col = bn + wn + jn * 8 + lc2;
            if (col < Nstore) {
                *(float2*)&C[(size_t)r0 * Nstore + col] =
                    make_float2(c[im][jn][0], c[im][jn][1]);
                *(float2*)&C[(size_t)(r0 + 8) * Nstore + col] =
                    make_float2(c[im][jn][2], c[im][jn][3]);
            }
        }
}

// ---------------- dt = softplus(raw + bias) ----------------
__global__ void dt_kernel(const float* __restrict__ zx,
                          const float* __restrict__ dt_bias,
                          float* __restrict__ dtb)
{
    int idx = blockIdx.x * blockDim.x + threadIdx.x;
    if (idx >= ROWS * NH) return;
    int h = idx & 63;
    int r = idx >> 6;
    dtb[idx] = softplus_f(zx[(size_t)r * DIP + DIN + CONVD + h] + dt_bias[h]);
}

// ---------------- causal conv1d (width 4) + SiLU, 4 rows/thread ----------
__global__ void conv_kernel(const float* __restrict__ zx,
                            const float* __restrict__ cw,
                            const float* __restrict__ cb,
                            float* __restrict__ out)
{
    int idx = blockIdx.x * blockDim.x + threadIdx.x;
    if (idx >= (ROWS / 4) * CONVD) return;
    int ch = idx % CONVD;
    int rb = idx / CONVD;
    int r0 = rb * 4;                    // 4 consecutive l in same batch
    int l0 = r0 & (LTOT - 1);

    float w0 = cw[ch * 4 + 0], w1 = cw[ch * 4 + 1];
    float w2 = cw[ch * 4 + 2], w3 = cw[ch * 4 + 3];
    float bias = cb[ch];

    float in[7];
#pragma unroll
    for (int w = 0; w < 7; w++) {
        int lw = l0 - 3 + w;
        in[w] = (lw >= 0)
              ? zx[(size_t)(r0 - 3 + w) * DIP + DIN + ch]
              : 0.f;
    }

#pragma unroll
    for (int j = 0; j < 4; j++) {
        float acc = bias + in[j] * w0 + in[j + 1] * w1
                         + in[j + 2] * w2 + in[j + 3] * w3;
        out[(size_t)(r0 + j) * CONVD + ch] = silu_f(acc);
    }
}

// ---------------- chunked SSD scan (256 threads, R11 version) ----------------
#define SSD_FLOATS (128*68 + 64*132 + 128*68 + 64*68 + 64*68 + 64*68 + 64*3)
#define SSD_SMEM   (SSD_FLOATS * 4)

__global__ __launch_bounds__(256) void ssd_kernel(
    const float* __restrict__ xbc, const float* __restrict__ dtb,
    const float* __restrict__ A_log, const float* __restrict__ D_param,
    float* __restrict__ y)
{
    extern __shared__ float sm[];
    float* sBt = sm;
    float* sC  = sBt + 128 * 68;
    float* sSt = sC  + 64 * 132;
    float* sX  = sSt + 128 * 68;
    float* sXd = sX  + 64 * 68;
    float* sG  = sXd + 64 * 68;
    float* sAc = sG  + 64 * 68;
    float* sW  = sAc + 64;
    float* sdt = sW  + 64;

    const int tid = threadIdx.x;
    const int b = blockIdx.x >> 6;
    const int h = blockIdx.x & 63;
    const int tr = tid >> 4, tc = tid & 15;
    const float Ah = -expf(A_log[h]);
    const float Dh = D_param[h];

    for (int i = tid; i < 128 * 68; i += 256) sSt[i] = 0.f;
    __syncthreads();

    for (int c = 0; c < NCHUNK; c++) {
        const int l0 = c * CK;
        const float* xb = xbc + (size_t)(b * LTOT + l0) * CONVD;

#pragma unroll
        for (int i = 0; i < 8; i++) {
            int idx = tid + i * 256;
            int l = idx >> 5, n4 = (idx & 31) << 2;
            float4 v = *(const float4*)(xb + (size_t)l * CONVD + DIN + n4);
            sBt[(n4 + 0) * 68 + l] = v.x;
            sBt[(n4 + 1) * 68 + l] = v.y;
            sBt[(n4 + 2) * 68 + l] = v.z;
            sBt[(n4 + 3) * 68 + l] = v.w;
            float4 u = *(const float4*)(xb + (size_t)l * CONVD + DIN + DS + n4);
            *(float4*)&sC[l * 132 + n4] = u;
        }
#pragma unroll
        for (int i = 0; i < 4; i++) {
            int idx = tid + i * 256;
            int l = idx >> 4, p4 = (idx & 15) << 2;
            *(float4*)&sX[l * 68 + p4] =
                *(const float4*)(xb + (size_t)l * CONVD + h * HD + p4);
        }
        if (tid < CK) sdt[tid] = dtb[(b * LTOT + l0 + tid) * NH + h];
        __syncthreads();

        if (tid == 0) {
            float a = 0.f;
            for (int l = 0; l < CK; l++) { a += Ah * sdt[l]; sAc[l] = a; }
            float at = a;
            for (int l = 0; l < CK; l++) sW[l] = expf(at - sAc[l]);
        }
#pragma unroll
        for (int i = 0; i < 16; i++) {
            int idx = tid + i * 256;
            int l = idx >> 6, p = idx & 63;
            sXd[l * 68 + p] = sX[l * 68 + p] * sdt[l];
        }
        __syncthreads();

        {
            float g[4][4];
#pragma unroll
            for (int i = 0; i < 4; i++)
#pragma unroll
                for (int j = 0; j < 4; j++) g[i][j] = 0.f;
            for (int nn = 0; nn < DS; nn++) {
                float cv[4];
#pragma unroll
                for (int i = 0; i < 4; i++) cv[i] = sC[(tr * 4 + i) * 132 + nn];
                float4 bv4 = *(float4*)&sBt[nn * 68 + tc * 4];
                float bv[4] = {bv4.x, bv4.y, bv4.z, bv4.w};
#pragma unroll
                for (int i = 0; i < 4; i++)
#pragma unroll
                    for (int j = 0; j < 4; j++)
                        g[i][j] += cv[i] * bv[j];
            }
#pragma unroll
            for (int i = 0; i < 4; i++) {
                int l = tr * 4 + i;
                float al = sAc[l];
                float o[4];
#pragma unroll
                for (int j = 0; j < 4; j++) {
                    int s = tc * 4 + j;
                    o[j] = (s <= l) ? g[i][j] * expf(al - sAc[s]) : 0.f;
                }
                *(float4*)&sG[l * 68 + tc * 4] = make_float4(o[0], o[1], o[2], o[3]);
            }
        }
        __syncthreads();

        {
            float yd[4][4], yo[4][4];
#pragma unroll
            for (int i = 0; i < 4; i++)
#pragma unroll
                for (int j = 0; j < 4; j++) { yd[i][j] = 0.f; yo[i][j] = 0.f; }
            for (int s = 0; s < CK; s++) {
                float gi[4];
#pragma unroll
                for (int i = 0; i < 4; i++) gi[i] = sG[(tr * 4 + i) * 68 + s];
                float4 xv4 = *(float4*)&sXd[s * 68 + tc * 4];
                float xv[4] = {xv4.x, xv4.y, xv4.z, xv4.w};
#pragma unroll
                for (int i = 0; i < 4; i++)
#pragma unroll
                    for (int j = 0; j < 4; j++)
                        yd[i][j] += gi[i] * xv[j];
            }
            for (int nn = 0; nn < DS; nn++) {
                float cv[4];
#pragma unroll
                for (int i = 0; i < 4; i++) cv[i] = sC[(tr * 4 + i) * 132 + nn];
                float4 sv4 = *(float4*)&sSt[nn * 68 + tc * 4];
                float sv[4] = {sv4.x, sv4.y, sv4.z, sv4.w};
#pragma unroll
                for (int i = 0; i < 4; i++)
#pragma unroll
                    for (int j = 0; j < 4; j++)
                        yo[i][j] += cv[i] * sv[j];
            }
#pragma unroll
            for (int i = 0; i < 4; i++) {
                int l = tr * 4 + i;
                float co = expf(sAc[l]);
                float o[4];
#pragma unroll
                for (int j = 0; j < 4; j++) {
                    int p = tc * 4 + j;
                    o[j] = yd[i][j] + co * yo[i][j] + Dh * sX[l * 68 + p];
                }
                *(float4*)(y + (size_t)(b * LTOT + l0 + l) * DIN + h * HD + tc * 4) =
                    make_float4(o[0], o[1], o[2], o[3]);
            }
        }
        __syncthreads();

        {
            float eT = expf(sAc[CK - 1]);
            float st[8][4];
#pragma unroll
            for (int k = 0; k < 8; k++) {
                float4 v = *(float4*)&sSt[(tr * 8 + k) * 68 + tc * 4];
                st[k][0] = v.x * eT; st[k][1] = v.y * eT;
                st[k][2] = v.z * eT; st[k][3] = v.w * eT;
            }
            for (int l = 0; l < CK; l++) {
                float wl = sW[l];
                float4 xv4 = *(float4*)&sXd[l * 68 + tc * 4];
                float xv[4] = {xv4.x, xv4.y, xv4.z, xv4.w};
#pragma unroll
                for (int k = 0; k < 8; k++) {
                    float bw = sBt[(tr * 8 + k) * 68 + l] * wl;
#pragma unroll
                    for (int j = 0; j < 4; j++)
                        st[k][j] += bw * xv[j];
                }
            }
#pragma unroll
            for (int k = 0; k < 8; k++)
                *(float4*)&sSt[(tr * 8 + k) * 68 + tc * 4] =
                    make_float4(st[k][0], st[k][1], st[k][2], st[k][3]);
        }
        __syncthreads();
    }
}

// ---------------- gating + RMSNorm, fused with fp16-split conversion ----
__global__ __launch_bounds__(256) void rms_kernel(
    const float* __restrict__ y, const float* __restrict__ zx,
    const float* __restrict__ nw, __half* __restrict__ A2)
{
    __shared__ float red[256];
    int row = blockIdx.x, tid = threadIdx.x;
    float v[16];
    float ss = 0.f;
#pragma unroll
    for (int i = 0; i < 16; i++) {
        int d = tid + i * 256;
        float yv = y[(size_t)row * DIN + d];
        float zv = zx[(size_t)row * DIP + d];
        float f = yv * silu_f(zv);
        v[i] = f;
        ss += f * f;
    }
    red[tid] = ss;
    __syncthreads();
    for (int s = 128; s > 0; s >>= 1) {
        if (tid < s) red[tid] += red[tid + s];
        __syncthreads();
    }
    float rr = rsqrtf(red[0] / (float)DIN + 1e-5f);
    __half* base = A2 + (size_t)row * (2 * DIN);
#pragma unroll
    for (int i = 0; i < 16; i++) {
        int d = tid + i * 256;
        float x = v[i] * rr * nw[d];
        __half h = __float2half_rn(x);
        __half l = __float2half_rn(x - __half2float(h));
        base[d] = h;
        base[DIN + d] = l;
    }
}

// ---------------- launch ----------------
extern "C" void kernel_launch(void* const* d_in, const int* in_sizes, int n_in,
                              void* d_out, int out_size)
{
    const float* u       = (const float*)d_in[0];
    const float* W_in    = (const float*)d_in[1];
    const float* conv_w  = (const float*)d_in[2];
    const float* conv_b  = (const float*)d_in[3];
    const float* dt_bias = (const float*)d_in[4];
    const float* A_log   = (const float*)d_in[5];
    const float* D_param = (const float*)d_in[6];
    const float* norm_w  = (const float*)d_in[7];
    const float* W_out   = (const float*)d_in[8];
    float* out = (float*)d_out;

    float *zx, *xbc, *dtb, *y;
    __half *hA1, *hB1, *hA2, *hB2;
    cudaGetSymbolAddress((void**)&zx,  g_zx);
    cudaGetSymbolAddress((void**)&xbc, g_xbc);
    cudaGetSymbolAddress((void**)&dtb, g_dt);
    cudaGetSymbolAddress((void**)&y,   g_y);
    cudaGetSymbolAddress((void**)&hA1, g_hA1);
    cudaGetSymbolAddress((void**)&hB1, g_hB1);
    cudaGetSymbolAddress((void**)&hA2, g_hA2);
    cudaGetSymbolAddress((void**)&hB2, g_hB2);

    cudaFuncSetAttribute(ssd_kernel,
                         cudaFuncAttributeMaxDynamicSharedMemorySize, SSD_SMEM);
    cudaFuncSetAttribute(gemm_fp16,
                         cudaFuncAttributeMaxDynamicSharedMemorySize, GG_SMEM);

    // 1) split-fp16 conversion + in-proj GEMM [4096,2048]@[2048,8512]
    convA<<<(int)(((size_t)ROWS * DM) / 256), 256>>>(u, hA1, DM);
    convB<<<dim3(NPAD1 / 32, DM / 32), dim3(32, 32)>>>(W_in, hB1, DM, DIP);
    gemm_fp16<<<dim3(NPAD1 / 256, ROWS / 128), 512, GG_SMEM>>>(hA1, hB1, zx,
                                                               DM, DIP);
    // 2) dt
    dt_kernel<<<(ROWS * NH + 255) / 256, 256>>>(zx, dt_bias, dtb);
    // 3) conv + silu (4 rows per thread)
    conv_kernel<<<((ROWS / 4) * CONVD + 255) / 256, 256>>>(zx, conv_w, conv_b, xbc);
    // 4) SSD (256 threads, R11 version)
    ssd_kernel<<<NBATCH * NH, 256, SSD_SMEM>>>(xbc, dtb, A_log, D_param, y);
    // 5) gate + RMSNorm (writes fp16 split operand directly)
    rms_kernel<<<ROWS, 256>>>(y, zx, norm_w, hA2);
    // 6) out-proj GEMM [4096,4096]@[4096,2048]
    convB<<<dim3(DM / 32, DIN / 32), dim3(32, 32)>>>(W_out, hB2, DIN, DM);
    gemm_fp16<<<dim3(DM / 256, ROWS / 128), 512, GG_SMEM>>>(hA2, hB2, out,
                                                            DIN, DM);
}